// round 15
// baseline (speedup 1.0000x reference)
#include <cuda_runtime.h>
#include <cuda_fp16.h>

#define HID 64
#define IN_DIM 128
#define NMAX 100000
#define EMAX 1600000

typedef unsigned long long u64;

// Scratch (__device__ globals: allocation-free rule)
__device__ float   g_p[NMAX * HID];
__device__ __half2 g_p16[NMAX * HID / 2];
__device__ float   g_agg[NMAX * HID];
__device__ int     g_deg[NMAX];
__device__ int     g_row[NMAX + 1];
__device__ int     g_cur[NMAX];
__device__ u64     g_bstate[128];
__device__ int     g_adj[EMAX];

static __device__ __forceinline__ unsigned h2_bits(__half2 h) {
    unsigned u;
    *(__half2*)&u = h;
    return u;
}

static __device__ __forceinline__ float lrelu(float v) {
    return v > 0.f ? v : 0.01f * v;
}

// --- packed dual-fp32 FMA (Blackwell f32x2; 2 MACs per issue slot) ---------
static __device__ __forceinline__ u64 pack2(float a, float b) {
    u64 r;
    asm("mov.b64 %0, {%1, %2};" : "=l"(r) : "f"(a), "f"(b));
    return r;
}
static __device__ __forceinline__ void fma2(u64& acc, u64 a, u64 b) {
    asm("fma.rn.f32x2 %0, %1, %2, %0;" : "+l"(acc) : "l"(a), "l"(b));
}
static __device__ __forceinline__ float2 unpack2(u64 v) {
    float2 f;
    asm("mov.b64 {%0, %1}, %2;" : "=f"(f.x), "=f"(f.y) : "l"(v));
    return f;
}

// ---------------------------------------------------------------------------
// CSR build
// ---------------------------------------------------------------------------
__global__ void k_zero(int* deg, u64* bstate, int n) {
    int i = blockIdx.x * blockDim.x + threadIdx.x;
    if (i < n) deg[i] = 0;
    if (i < 128) bstate[i] = 0ull;
}

__global__ void k_hist(const int* __restrict__ dst, int* deg, int E) {
    int i = blockIdx.x * blockDim.x + threadIdx.x;
    if (i < E) atomicAdd(&deg[dst[i]], 1);
}

// Single-kernel exclusive scan of deg -> row & cur, via decoupled lookback.
__global__ void k_scanLB(const int* __restrict__ deg,
                         int* row, int* cur, u64* bstate,
                         int M, int nblk) {
    __shared__ int wsum[32];
    __shared__ int s_prev;
    const int tid = threadIdx.x;
    const int bid = blockIdx.x;
    const int i = bid * 1024 + tid;
    const int v = (i < M) ? deg[i] : 0;

    int x = v;
#pragma unroll
    for (int o = 1; o < 32; o <<= 1) {
        int t = __shfl_up_sync(0xffffffffu, x, o);
        if ((tid & 31) >= o) x += t;
    }
    if ((tid & 31) == 31) wsum[tid >> 5] = x;
    __syncthreads();
    if (tid < 32) {
        int y = wsum[tid];
#pragma unroll
        for (int o = 1; o < 32; o <<= 1) {
            int t = __shfl_up_sync(0xffffffffu, y, o);
            if (tid >= o) y += t;
        }
        wsum[tid] = y;
    }
    __syncthreads();
    const int base = (tid >= 32) ? wsum[(tid >> 5) - 1] : 0;
    const int incl = x + base;
    const int btotal = wsum[31];

    if (tid == 0) {
        u64 st = ((u64)(bid == 0 ? 2 : 1) << 62) | (unsigned)btotal;
        atomicExch(&bstate[bid], st);
        if (bid == 0) s_prev = 0;
    }

    if (bid > 0 && tid < 32) {
        int base_idx = bid - 1;
        int running = 0;
        while (true) {
            const int idx = base_idx - tid;
            u64 st;
            unsigned flag;
            do {
                st = (idx >= 0) ? atomicAdd(&bstate[idx], 0ull)
                                : ((u64)2 << 62);
                flag = (unsigned)(st >> 62);
            } while (flag == 0);
            const unsigned pre_mask = __ballot_sync(0xffffffffu, flag == 2);
            int val = (int)(st & 0xffffffffu);
            if (pre_mask) {
                const int p = __ffs(pre_mask) - 1;
                int contrib = (tid <= p) ? val : 0;
#pragma unroll
                for (int o = 16; o; o >>= 1)
                    contrib += __shfl_down_sync(0xffffffffu, contrib, o);
                running += __shfl_sync(0xffffffffu, contrib, 0);
                break;
            } else {
                int contrib = val;
#pragma unroll
                for (int o = 16; o; o >>= 1)
                    contrib += __shfl_down_sync(0xffffffffu, contrib, o);
                running += __shfl_sync(0xffffffffu, contrib, 0);
                base_idx -= 32;
            }
        }
        if (tid == 0) {
            s_prev = running;
            atomicExch(&bstate[bid], ((u64)2 << 62) | (unsigned)(running + btotal));
        }
    }
    __syncthreads();

    const int prev = s_prev;
    if (i < M) {
        const int r = prev + incl - v;
        row[i] = r;
        cur[i] = r;
    }
    if (bid == nblk - 1 && tid == 1023) row[M] = prev + incl;
}

__global__ void k_fill(const int* __restrict__ src, const int* __restrict__ dst,
                       int* cur, int* adj, int E) {
    int i = blockIdx.x * blockDim.x + threadIdx.x;
    if (i < E) {
        int pos = atomicAdd(&cur[dst[i]], 1);
        adj[pos] = src[i];
    }
}

// ---------------------------------------------------------------------------
// Gather-sum over fp16 rows (warp per node, MLP=4)
// ---------------------------------------------------------------------------
__global__ __launch_bounds__(256)
void k_gather(const __half2* __restrict__ p16,
              const int* __restrict__ row,
              const int* __restrict__ adj,
              float* __restrict__ agg, int M) {
    const int w = (blockIdx.x * blockDim.x + threadIdx.x) >> 5;
    if (w >= M) return;
    const int lane = threadIdx.x & 31;
    const int beg = __ldg(&row[w]);
    const int end = __ldg(&row[w + 1]);
    float sx = 0.f, sy = 0.f;
    int j = beg;
    for (; j + 3 < end; j += 4) {
        const int u0 = __ldg(&adj[j]);
        const int u1 = __ldg(&adj[j + 1]);
        const int u2 = __ldg(&adj[j + 2]);
        const int u3 = __ldg(&adj[j + 3]);
        const float2 f0 = __half22float2(__ldg(&p16[(size_t)u0 * 32 + lane]));
        const float2 f1 = __half22float2(__ldg(&p16[(size_t)u1 * 32 + lane]));
        const float2 f2 = __half22float2(__ldg(&p16[(size_t)u2 * 32 + lane]));
        const float2 f3 = __half22float2(__ldg(&p16[(size_t)u3 * 32 + lane]));
        sx += (f0.x + f1.x) + (f2.x + f3.x);
        sy += (f0.y + f1.y) + (f2.y + f3.y);
    }
    for (; j < end; j++) {
        const int u = __ldg(&adj[j]);
        const float2 f = __half22float2(__ldg(&p16[(size_t)u * 32 + lane]));
        sx += f.x;
        sy += f.y;
    }
    ((float2*)agg)[(size_t)w * 32 + lane] = make_float2(sx, sy);
}

// ---------------------------------------------------------------------------
// f32x2 core over a 128-row tile: 4 rows x 8 cols per thread (acc[4][4] u64).
// tx = tid&7 (col group), ty = tid>>3 in 0..31, rows = ty + 32*i, i=0..3.
// ---------------------------------------------------------------------------
template <int K, int S>
static __device__ __forceinline__
void mma_f32x2(const float* __restrict__ Xs, const float* __restrict__ Ws,
               int tx, int ty, u64 acc[4][4]) {
#pragma unroll
    for (int i = 0; i < 4; i++)
#pragma unroll
        for (int j = 0; j < 4; j++) acc[i][j] = 0ull;

#pragma unroll 4
    for (int k = 0; k < K; k += 2) {
        const ulonglong2 wa01 = *(const ulonglong2*)&Ws[k * 64 + tx * 8];
        const ulonglong2 wa23 = *(const ulonglong2*)&Ws[k * 64 + tx * 8 + 4];
        const ulonglong2 wb01 = *(const ulonglong2*)&Ws[(k + 1) * 64 + tx * 8];
        const ulonglong2 wb23 = *(const ulonglong2*)&Ws[(k + 1) * 64 + tx * 8 + 4];
#pragma unroll
        for (int i = 0; i < 4; i++) {
            const float2 x = *(const float2*)&Xs[(ty + 32 * i) * S + k];
            const u64 xa = pack2(x.x, x.x);
            const u64 xb = pack2(x.y, x.y);
            fma2(acc[i][0], xa, wa01.x); fma2(acc[i][1], xa, wa01.y);
            fma2(acc[i][2], xa, wa23.x); fma2(acc[i][3], xa, wa23.y);
            fma2(acc[i][0], xb, wb01.x); fma2(acc[i][1], xb, wb01.y);
            fma2(acc[i][2], xb, wb23.x); fma2(acc[i][3], xb, wb23.y);
        }
    }
}

// ---------------------------------------------------------------------------
// GEMM: Y[M,64] = f(X) @ W[K,64]   (block tile 128x64, 256 threads)
// K=128: smem 99.6KB -> 2 blocks/SM (16 warps); K=64: 51.2KB -> 3 blocks (24 warps)
// ---------------------------------------------------------------------------
template <int K, bool CONSUME>
__global__ __launch_bounds__(256, (K == 128 ? 2 : 3))
void gemm64_kernel(const float* __restrict__ X1,
                   const float* __restrict__ X2,
                   const float* __restrict__ ba,
                   const float* __restrict__ W,
                   const float* __restrict__ bb,
                   float* __restrict__ Y,
                   __half2* __restrict__ P16,
                   int M) {
    constexpr int S  = K + 4;
    constexpr int KC = K / 4;
    extern __shared__ float smem[];
    float* Xs = smem;             // 128 * S
    float* Ws = smem + 128 * S;   // K * 64

    const int tid = threadIdx.x;
    const int m0  = blockIdx.x * 128;

    for (int i = tid; i < K * 16; i += 256)
        ((float4*)Ws)[i] = ((const float4*)W)[i];

    for (int i = tid; i < 128 * KC; i += 256) {
        const int r  = i / KC;
        const int kc = i % KC;
        const int m  = m0 + r;
        float4 v = make_float4(0.f, 0.f, 0.f, 0.f);
        if (m < M) {
            v = ((const float4*)(X1 + (size_t)m * K))[kc];
            if (CONSUME) {
                float4 a = ((const float4*)(X2 + (size_t)m * K))[kc];
                float4 b = ((const float4*)ba)[kc];
                v.x = fmaxf(v.x + a.x + b.x, 0.f);
                v.y = fmaxf(v.y + a.y + b.y, 0.f);
                v.z = fmaxf(v.z + a.z + b.z, 0.f);
                v.w = fmaxf(v.w + a.w + b.w, 0.f);
            }
        }
        *(float4*)&Xs[r * S + kc * 4] = v;
    }
    __syncthreads();

    const int tx = tid & 7;
    const int ty = tid >> 3;

    u64 acc[4][4];
    mma_f32x2<K, S>(Xs, Ws, tx, ty, acc);

    float4 b0 = make_float4(0.f, 0.f, 0.f, 0.f);
    float4 b1 = make_float4(0.f, 0.f, 0.f, 0.f);
    if (CONSUME) {
        b0 = ((const float4*)bb)[tx * 2];
        b1 = ((const float4*)bb)[tx * 2 + 1];
    }

#pragma unroll
    for (int i = 0; i < 4; i++) {
        const int m = m0 + ty + 32 * i;
        if (m < M) {
            const float2 e0 = unpack2(acc[i][0]);
            const float2 e1 = unpack2(acc[i][1]);
            const float2 e2 = unpack2(acc[i][2]);
            const float2 e3 = unpack2(acc[i][3]);
            float4 o0, o1;
            o0.x = e0.x + b0.x; o0.y = e0.y + b0.y;
            o0.z = e1.x + b0.z; o0.w = e1.y + b0.w;
            o1.x = e2.x + b1.x; o1.y = e2.y + b1.y;
            o1.z = e3.x + b1.z; o1.w = e3.y + b1.w;
            if (CONSUME) {
                o0.x = lrelu(o0.x); o0.y = lrelu(o0.y);
                o0.z = lrelu(o0.z); o0.w = lrelu(o0.w);
                o1.x = lrelu(o1.x); o1.y = lrelu(o1.y);
                o1.z = lrelu(o1.z); o1.w = lrelu(o1.w);
            }
            float4* yr = (float4*)(Y + (size_t)m * 64);
            yr[tx * 2]     = o0;
            yr[tx * 2 + 1] = o1;
            if (!CONSUME) {
                uint4 pk;
                pk.x = h2_bits(__floats2half2_rn(o0.x, o0.y));
                pk.y = h2_bits(__floats2half2_rn(o0.z, o0.w));
                pk.z = h2_bits(__floats2half2_rn(o1.x, o1.y));
                pk.w = h2_bits(__floats2half2_rn(o1.z, o1.w));
                *(uint4*)&P16[(size_t)m * 32 + tx * 4] = pk;
            }
        }
    }
}

// ---------------------------------------------------------------------------
// Fused mid kernel (128-row tile, 256 threads):
//   h1 = leaky( relu(p + agg + b1a) @ W1b + b1b )   (stays in smem)
//   p2 = h1 @ W2a;  p2_16 = fp16(p2)
// ---------------------------------------------------------------------------
__global__ __launch_bounds__(256, 3)
void fused_mid_kernel(const float* __restrict__ p,
                      const float* __restrict__ agg,
                      const float* __restrict__ b1a,
                      const float* __restrict__ W1b,
                      const float* __restrict__ b1b,
                      const float* __restrict__ W2a,
                      float* __restrict__ p2,
                      __half2* __restrict__ p2_16,
                      int M) {
    constexpr int K = 64, S = 68, KC = 16;
    extern __shared__ float smem[];
    float* Xs = smem;             // 128 * 68
    float* Ws = smem + 128 * S;   // 64 * 64

    const int tid = threadIdx.x;
    const int m0  = blockIdx.x * 128;
    const int tx  = tid & 7;
    const int ty  = tid >> 3;

    for (int i = tid; i < K * 16; i += 256)
        ((float4*)Ws)[i] = ((const float4*)W1b)[i];
    for (int i = tid; i < 128 * KC; i += 256) {
        const int r  = i / KC;
        const int kc = i % KC;
        const int m  = m0 + r;
        float4 v = make_float4(0.f, 0.f, 0.f, 0.f);
        if (m < M) {
            v = ((const float4*)(p + (size_t)m * K))[kc];
            float4 a = ((const float4*)(agg + (size_t)m * K))[kc];
            float4 b = ((const float4*)b1a)[kc];
            v.x = fmaxf(v.x + a.x + b.x, 0.f);
            v.y = fmaxf(v.y + a.y + b.y, 0.f);
            v.z = fmaxf(v.z + a.z + b.z, 0.f);
            v.w = fmaxf(v.w + a.w + b.w, 0.f);
        }
        *(float4*)&Xs[r * S + kc * 4] = v;
    }
    __syncthreads();

    u64 acc[4][4];
    mma_f32x2<K, S>(Xs, Ws, tx, ty, acc);

    const float4 c0 = ((const float4*)b1b)[tx * 2];
    const float4 c1 = ((const float4*)b1b)[tx * 2 + 1];

    __syncthreads();   // all reads of Xs/Ws done before overwrite

    // ---- h1 tile -> Xs (zeros beyond M); Ws <- W2a ----
#pragma unroll
    for (int i = 0; i < 4; i++) {
        const int r = ty + 32 * i;
        const int m = m0 + r;
        float4 o0 = make_float4(0.f, 0.f, 0.f, 0.f);
        float4 o1 = make_float4(0.f, 0.f, 0.f, 0.f);
        if (m < M) {
            const float2 e0 = unpack2(acc[i][0]);
            const float2 e1 = unpack2(acc[i][1]);
            const float2 e2 = unpack2(acc[i][2]);
            const float2 e3 = unpack2(acc[i][3]);
            o0.x = lrelu(e0.x + c0.x); o0.y = lrelu(e0.y + c0.y);
            o0.z = lrelu(e1.x + c0.z); o0.w = lrelu(e1.y + c0.w);
            o1.x = lrelu(e2.x + c1.x); o1.y = lrelu(e2.y + c1.y);
            o1.z = lrelu(e3.x + c1.z); o1.w = lrelu(e3.y + c1.w);
        }
        *(float4*)&Xs[r * S + tx * 8]     = o0;
        *(float4*)&Xs[r * S + tx * 8 + 4] = o1;
    }
    for (int i = tid; i < K * 16; i += 256)
        ((float4*)Ws)[i] = ((const float4*)W2a)[i];
    __syncthreads();

    // ---- Stage 2: p2 = h1 @ W2a ----
    mma_f32x2<K, S>(Xs, Ws, tx, ty, acc);

#pragma unroll
    for (int i = 0; i < 4; i++) {
        const int m = m0 + ty + 32 * i;
        if (m < M) {
            const float2 e0 = unpack2(acc[i][0]);
            const float2 e1 = unpack2(acc[i][1]);
            const float2 e2 = unpack2(acc[i][2]);
            const float2 e3 = unpack2(acc[i][3]);
            float4 o0, o1;
            o0.x = e0.x; o0.y = e0.y; o0.z = e1.x; o0.w = e1.y;
            o1.x = e2.x; o1.y = e2.y; o1.z = e3.x; o1.w = e3.y;
            float4* yr = (float4*)(p2 + (size_t)m * 64);
            yr[tx * 2]     = o0;
            yr[tx * 2 + 1] = o1;
            uint4 pk;
            pk.x = h2_bits(__floats2half2_rn(o0.x, o0.y));
            pk.y = h2_bits(__floats2half2_rn(o0.z, o0.w));
            pk.z = h2_bits(__floats2half2_rn(o1.x, o1.y));
            pk.w = h2_bits(__floats2half2_rn(o1.z, o1.w));
            *(uint4*)&p2_16[(size_t)m * 32 + tx * 4] = pk;
        }
    }
}

// ---------------------------------------------------------------------------
extern "C" void kernel_launch(void* const* d_in, const int* in_sizes, int n_in,
                              void* d_out, int out_size) {
    const float* h   = (const float*)d_in[0];
    const int*   ei  = (const int*)d_in[1];
    const float* W1a = (const float*)d_in[2];
    const float* b1a = (const float*)d_in[3];
    const float* W1b = (const float*)d_in[4];
    const float* b1b = (const float*)d_in[5];
    const float* W2a = (const float*)d_in[6];
    const float* b2a = (const float*)d_in[7];
    const float* W2b = (const float*)d_in[8];
    const float* b2b = (const float*)d_in[9];
    float* out = (float*)d_out;

    const int M = in_sizes[0] / IN_DIM;   // 100000
    const int E = in_sizes[1] / 2;        // 1600000
    const int* src = ei;
    const int* dst = ei + E;

    float *p, *agg;
    __half2* p16;
    int *deg, *row, *cur, *adj;
    u64* bstate;
    cudaGetSymbolAddress((void**)&p,      g_p);
    cudaGetSymbolAddress((void**)&p16,    g_p16);
    cudaGetSymbolAddress((void**)&agg,    g_agg);
    cudaGetSymbolAddress((void**)&deg,    g_deg);
    cudaGetSymbolAddress((void**)&row,    g_row);
    cudaGetSymbolAddress((void**)&cur,    g_cur);
    cudaGetSymbolAddress((void**)&bstate, g_bstate);
    cudaGetSymbolAddress((void**)&adj,    g_adj);

    const int nblk = (M + 1023) / 1024;

    const int gblocks = (M + 127) / 128;        // 782
    const int wblocks = (M * 32 + 255) / 256;   // warp-per-node gather
    const int smem128 = (128 * (128 + 4) + 128 * 64) * 4;  // 100352 B
    const int smem64  = (128 * (64 + 4)  + 64 * 64)  * 4;  // 51200 B

    cudaFuncSetAttribute(gemm64_kernel<128, false>,
                         cudaFuncAttributeMaxDynamicSharedMemorySize, smem128);
    cudaFuncSetAttribute(gemm64_kernel<64, true>,
                         cudaFuncAttributeMaxDynamicSharedMemorySize, smem64);
    cudaFuncSetAttribute(fused_mid_kernel,
                         cudaFuncAttributeMaxDynamicSharedMemorySize, smem64);

    // ---- CSR build + layer-1 producer (gemm128 stays at launch index 3
    //      so the ncu window lands on it) ----
    k_zero<<<(M + 255) / 256, 256>>>(deg, bstate, M);
    k_hist<<<(E + 255) / 256, 256>>>(dst, deg, E);
    k_scanLB<<<nblk, 1024>>>(deg, row, cur, bstate, M, nblk);
    gemm64_kernel<128, false><<<gblocks, 256, smem128>>>(h, nullptr, nullptr,
                                                         W1a, nullptr, p, p16, M);
    k_fill<<<(E + 255) / 256, 256>>>(src, dst, cur, adj, E);

    k_gather<<<wblocks, 256>>>(p16, row, adj, agg, M);
    fused_mid_kernel<<<gblocks, 256, smem64>>>(p, agg, b1a, W1b, b1b, W2a,
                                               p, p16, M);
    k_gather<<<wblocks, 256>>>(p16, row, adj, agg, M);
    gemm64_kernel<64, true><<<gblocks, 256, smem64>>>(p, agg, b2a,
                                                      W2b, b2b, out, nullptr, M);
}

// round 16
// speedup vs baseline: 1.1688x; 1.1688x over previous
#include <cuda_runtime.h>
#include <cuda_fp16.h>

#define HID 64
#define IN_DIM 128
#define NMAX 100000
#define EMAX 1600000

typedef unsigned long long u64;

// Scratch (__device__ globals: allocation-free rule)
__device__ float   g_p[NMAX * HID];
__device__ __half2 g_p16[NMAX * HID / 2];
__device__ float   g_agg[NMAX * HID];
__device__ int     g_deg[NMAX];
__device__ int     g_row[NMAX + 1];
__device__ int     g_cur[NMAX];
__device__ u64     g_bstate[128];
__device__ int     g_adj[EMAX];

static __device__ __forceinline__ unsigned h2_bits(__half2 h) {
    unsigned u;
    *(__half2*)&u = h;
    return u;
}

static __device__ __forceinline__ float lrelu(float v) {
    return v > 0.f ? v : 0.01f * v;
}

// --- packed dual-fp32 FMA (Blackwell f32x2; 2 MACs per issue slot) ---------
static __device__ __forceinline__ u64 pack2(float a, float b) {
    u64 r;
    asm("mov.b64 %0, {%1, %2};" : "=l"(r) : "f"(a), "f"(b));
    return r;
}
static __device__ __forceinline__ void fma2(u64& acc, u64 a, u64 b) {
    asm("fma.rn.f32x2 %0, %1, %2, %0;" : "+l"(acc) : "l"(a), "l"(b));
}
static __device__ __forceinline__ float2 unpack2(u64 v) {
    float2 f;
    asm("mov.b64 {%0, %1}, %2;" : "=f"(f.x), "=f"(f.y) : "l"(v));
    return f;
}

// ---------------------------------------------------------------------------
// CSR build
// ---------------------------------------------------------------------------
__global__ void k_zero(int* deg, u64* bstate, int n) {
    int i = blockIdx.x * blockDim.x + threadIdx.x;
    if (i < n) deg[i] = 0;
    if (i < 128) bstate[i] = 0ull;
}

__global__ void k_hist(const int* __restrict__ dst, int* deg, int E) {
    int i = blockIdx.x * blockDim.x + threadIdx.x;
    if (i < E) atomicAdd(&deg[dst[i]], 1);
}

// Single-kernel exclusive scan of deg -> row & cur, via decoupled lookback.
__global__ void k_scanLB(const int* __restrict__ deg,
                         int* row, int* cur, u64* bstate,
                         int M, int nblk) {
    __shared__ int wsum[32];
    __shared__ int s_prev;
    const int tid = threadIdx.x;
    const int bid = blockIdx.x;
    const int i = bid * 1024 + tid;
    const int v = (i < M) ? deg[i] : 0;

    int x = v;
#pragma unroll
    for (int o = 1; o < 32; o <<= 1) {
        int t = __shfl_up_sync(0xffffffffu, x, o);
        if ((tid & 31) >= o) x += t;
    }
    if ((tid & 31) == 31) wsum[tid >> 5] = x;
    __syncthreads();
    if (tid < 32) {
        int y = wsum[tid];
#pragma unroll
        for (int o = 1; o < 32; o <<= 1) {
            int t = __shfl_up_sync(0xffffffffu, y, o);
            if (tid >= o) y += t;
        }
        wsum[tid] = y;
    }
    __syncthreads();
    const int base = (tid >= 32) ? wsum[(tid >> 5) - 1] : 0;
    const int incl = x + base;
    const int btotal = wsum[31];

    if (tid == 0) {
        u64 st = ((u64)(bid == 0 ? 2 : 1) << 62) | (unsigned)btotal;
        atomicExch(&bstate[bid], st);
        if (bid == 0) s_prev = 0;
    }

    if (bid > 0 && tid < 32) {
        int base_idx = bid - 1;
        int running = 0;
        while (true) {
            const int idx = base_idx - tid;
            u64 st;
            unsigned flag;
            do {
                st = (idx >= 0) ? atomicAdd(&bstate[idx], 0ull)
                                : ((u64)2 << 62);
                flag = (unsigned)(st >> 62);
            } while (flag == 0);
            const unsigned pre_mask = __ballot_sync(0xffffffffu, flag == 2);
            int val = (int)(st & 0xffffffffu);
            if (pre_mask) {
                const int p = __ffs(pre_mask) - 1;
                int contrib = (tid <= p) ? val : 0;
#pragma unroll
                for (int o = 16; o; o >>= 1)
                    contrib += __shfl_down_sync(0xffffffffu, contrib, o);
                running += __shfl_sync(0xffffffffu, contrib, 0);
                break;
            } else {
                int contrib = val;
#pragma unroll
                for (int o = 16; o; o >>= 1)
                    contrib += __shfl_down_sync(0xffffffffu, contrib, o);
                running += __shfl_sync(0xffffffffu, contrib, 0);
                base_idx -= 32;
            }
        }
        if (tid == 0) {
            s_prev = running;
            atomicExch(&bstate[bid], ((u64)2 << 62) | (unsigned)(running + btotal));
        }
    }
    __syncthreads();

    const int prev = s_prev;
    if (i < M) {
        const int r = prev + incl - v;
        row[i] = r;
        cur[i] = r;
    }
    if (bid == nblk - 1 && tid == 1023) row[M] = prev + incl;
}

__global__ void k_fill(const int* __restrict__ src, const int* __restrict__ dst,
                       int* cur, int* adj, int E) {
    int i = blockIdx.x * blockDim.x + threadIdx.x;
    if (i < E) {
        int pos = atomicAdd(&cur[dst[i]], 1);
        adj[pos] = src[i];
    }
}

// ---------------------------------------------------------------------------
// Gather-sum over fp16 rows (warp per node, MLP=4)
// ---------------------------------------------------------------------------
__global__ __launch_bounds__(256)
void k_gather(const __half2* __restrict__ p16,
              const int* __restrict__ row,
              const int* __restrict__ adj,
              float* __restrict__ agg, int M) {
    const int w = (blockIdx.x * blockDim.x + threadIdx.x) >> 5;
    if (w >= M) return;
    const int lane = threadIdx.x & 31;
    const int beg = __ldg(&row[w]);
    const int end = __ldg(&row[w + 1]);
    float sx = 0.f, sy = 0.f;
    int j = beg;
    for (; j + 3 < end; j += 4) {
        const int u0 = __ldg(&adj[j]);
        const int u1 = __ldg(&adj[j + 1]);
        const int u2 = __ldg(&adj[j + 2]);
        const int u3 = __ldg(&adj[j + 3]);
        const float2 f0 = __half22float2(__ldg(&p16[(size_t)u0 * 32 + lane]));
        const float2 f1 = __half22float2(__ldg(&p16[(size_t)u1 * 32 + lane]));
        const float2 f2 = __half22float2(__ldg(&p16[(size_t)u2 * 32 + lane]));
        const float2 f3 = __half22float2(__ldg(&p16[(size_t)u3 * 32 + lane]));
        sx += (f0.x + f1.x) + (f2.x + f3.x);
        sy += (f0.y + f1.y) + (f2.y + f3.y);
    }
    for (; j < end; j++) {
        const int u = __ldg(&adj[j]);
        const float2 f = __half22float2(__ldg(&p16[(size_t)u * 32 + lane]));
        sx += f.x;
        sy += f.y;
    }
    ((float2*)agg)[(size_t)w * 32 + lane] = make_float2(sx, sy);
}

// ---------------------------------------------------------------------------
// f32x2 core over a 256-row tile, 64-wide K-chunk: 8 rows x 8 cols per thread.
// Accumulates into acc (no zeroing here). Wc points at the W rows of this
// chunk. Xs stride S = 68.
// ---------------------------------------------------------------------------
static __device__ __forceinline__
void mma_chunk(const float* __restrict__ Xs, const float* __restrict__ Wc,
               int tx, int ty, u64 acc[8][4]) {
    constexpr int S = 68;
#pragma unroll 4
    for (int k = 0; k < 64; k += 2) {
        const ulonglong2 wa01 = *(const ulonglong2*)&Wc[k * 64 + tx * 8];
        const ulonglong2 wa23 = *(const ulonglong2*)&Wc[k * 64 + tx * 8 + 4];
        const ulonglong2 wb01 = *(const ulonglong2*)&Wc[(k + 1) * 64 + tx * 8];
        const ulonglong2 wb23 = *(const ulonglong2*)&Wc[(k + 1) * 64 + tx * 8 + 4];
#pragma unroll
        for (int i = 0; i < 8; i++) {
            const float2 x = *(const float2*)&Xs[(ty + 32 * i) * S + k];
            const u64 xa = pack2(x.x, x.x);
            const u64 xb = pack2(x.y, x.y);
            fma2(acc[i][0], xa, wa01.x); fma2(acc[i][1], xa, wa01.y);
            fma2(acc[i][2], xa, wa23.x); fma2(acc[i][3], xa, wa23.y);
            fma2(acc[i][0], xb, wb01.x); fma2(acc[i][1], xb, wb01.y);
            fma2(acc[i][2], xb, wb23.x); fma2(acc[i][3], xb, wb23.y);
        }
    }
}

// ---------------------------------------------------------------------------
// GEMM: Y[M,64] = f(X) @ W[K,64]   (block tile 256x64, 256 threads)
// Xs holds a 64-wide K-chunk (256*68 floats); W is fully resident (K*64).
// smem: K=128 -> 102.4KB (2 blocks/SM, 16 warps); K=64 -> 86KB (2 blocks/SM).
// CONSUME=false: x = X1;              Y = X@W;  also writes P16 = fp16(Y)
// CONSUME=true : x = relu(X1+X2+ba);  Y = leaky(X@W + bb)   (K=64 only)
// ---------------------------------------------------------------------------
template <int K, bool CONSUME>
__global__ __launch_bounds__(256, 2)
void gemm64_kernel(const float* __restrict__ X1,
                   const float* __restrict__ X2,
                   const float* __restrict__ ba,
                   const float* __restrict__ W,
                   const float* __restrict__ bb,
                   float* __restrict__ Y,
                   __half2* __restrict__ P16,
                   int M) {
    constexpr int S = 68;
    extern __shared__ float smem[];
    float* Xs = smem;             // 256 * 68 (one 64-wide K chunk)
    float* Ws = smem + 256 * S;   // K * 64 (full)

    const int tid = threadIdx.x;
    const int m0  = blockIdx.x * 256;
    const int tx  = tid & 7;
    const int ty  = tid >> 3;

    // Load full W
    for (int i = tid; i < K * 16; i += 256)
        ((float4*)Ws)[i] = ((const float4*)W)[i];

    u64 acc[8][4];
#pragma unroll
    for (int i = 0; i < 8; i++)
#pragma unroll
        for (int j = 0; j < 4; j++) acc[i][j] = 0ull;

#pragma unroll
    for (int kk = 0; kk < K; kk += 64) {
        if (kk > 0) __syncthreads();   // all warps done with previous chunk
        // Load 64-wide X chunk (fused transform)
        for (int i = tid; i < 256 * 16; i += 256) {
            const int r  = i / 16;
            const int kc = i % 16;
            const int m  = m0 + r;
            float4 v = make_float4(0.f, 0.f, 0.f, 0.f);
            if (m < M) {
                v = ((const float4*)(X1 + (size_t)m * K + kk))[kc];
                if (CONSUME) {
                    float4 a = ((const float4*)(X2 + (size_t)m * K + kk))[kc];
                    float4 b = ((const float4*)(ba + kk))[kc];
                    v.x = fmaxf(v.x + a.x + b.x, 0.f);
                    v.y = fmaxf(v.y + a.y + b.y, 0.f);
                    v.z = fmaxf(v.z + a.z + b.z, 0.f);
                    v.w = fmaxf(v.w + a.w + b.w, 0.f);
                }
            }
            *(float4*)&Xs[r * S + kc * 4] = v;
        }
        __syncthreads();
        mma_chunk(Xs, Ws + kk * 64, tx, ty, acc);
    }

    float4 b0 = make_float4(0.f, 0.f, 0.f, 0.f);
    float4 b1 = make_float4(0.f, 0.f, 0.f, 0.f);
    if (CONSUME) {
        b0 = ((const float4*)bb)[tx * 2];
        b1 = ((const float4*)bb)[tx * 2 + 1];
    }

#pragma unroll
    for (int i = 0; i < 8; i++) {
        const int m = m0 + ty + 32 * i;
        if (m < M) {
            const float2 e0 = unpack2(acc[i][0]);
            const float2 e1 = unpack2(acc[i][1]);
            const float2 e2 = unpack2(acc[i][2]);
            const float2 e3 = unpack2(acc[i][3]);
            float4 o0, o1;
            o0.x = e0.x + b0.x; o0.y = e0.y + b0.y;
            o0.z = e1.x + b0.z; o0.w = e1.y + b0.w;
            o1.x = e2.x + b1.x; o1.y = e2.y + b1.y;
            o1.z = e3.x + b1.z; o1.w = e3.y + b1.w;
            if (CONSUME) {
                o0.x = lrelu(o0.x); o0.y = lrelu(o0.y);
                o0.z = lrelu(o0.z); o0.w = lrelu(o0.w);
                o1.x = lrelu(o1.x); o1.y = lrelu(o1.y);
                o1.z = lrelu(o1.z); o1.w = lrelu(o1.w);
            }
            float4* yr = (float4*)(Y + (size_t)m * 64);
            yr[tx * 2]     = o0;
            yr[tx * 2 + 1] = o1;
            if (!CONSUME) {
                uint4 pk;
                pk.x = h2_bits(__floats2half2_rn(o0.x, o0.y));
                pk.y = h2_bits(__floats2half2_rn(o0.z, o0.w));
                pk.z = h2_bits(__floats2half2_rn(o1.x, o1.y));
                pk.w = h2_bits(__floats2half2_rn(o1.z, o1.w));
                *(uint4*)&P16[(size_t)m * 32 + tx * 4] = pk;
            }
        }
    }
}

// ---------------------------------------------------------------------------
// Fused mid kernel (256-row tile, 256 threads):
//   h1 = leaky( relu(p + agg + b1a) @ W1b + b1b )   (stays in smem)
//   p2 = h1 @ W2a;  p2_16 = fp16(p2)
// ---------------------------------------------------------------------------
__global__ __launch_bounds__(256, 2)
void fused_mid_kernel(const float* __restrict__ p,
                      const float* __restrict__ agg,
                      const float* __restrict__ b1a,
                      const float* __restrict__ W1b,
                      const float* __restrict__ b1b,
                      const float* __restrict__ W2a,
                      float* __restrict__ p2,
                      __half2* __restrict__ p2_16,
                      int M) {
    constexpr int S = 68, KC = 16;
    extern __shared__ float smem[];
    float* Xs = smem;             // 256 * 68
    float* Ws = smem + 256 * S;   // 64 * 64

    const int tid = threadIdx.x;
    const int m0  = blockIdx.x * 256;
    const int tx  = tid & 7;
    const int ty  = tid >> 3;

    // ---- Stage 1 load: Ws = W1b, Xs = relu(p + agg + b1a) ----
    for (int i = tid; i < 64 * 16; i += 256)
        ((float4*)Ws)[i] = ((const float4*)W1b)[i];
    for (int i = tid; i < 256 * KC; i += 256) {
        const int r  = i / KC;
        const int kc = i % KC;
        const int m  = m0 + r;
        float4 v = make_float4(0.f, 0.f, 0.f, 0.f);
        if (m < M) {
            v = ((const float4*)(p + (size_t)m * 64))[kc];
            float4 a = ((const float4*)(agg + (size_t)m * 64))[kc];
            float4 b = ((const float4*)b1a)[kc];
            v.x = fmaxf(v.x + a.x + b.x, 0.f);
            v.y = fmaxf(v.y + a.y + b.y, 0.f);
            v.z = fmaxf(v.z + a.z + b.z, 0.f);
            v.w = fmaxf(v.w + a.w + b.w, 0.f);
        }
        *(float4*)&Xs[r * S + kc * 4] = v;
    }
    __syncthreads();

    u64 acc[8][4];
#pragma unroll
    for (int i = 0; i < 8; i++)
#pragma unroll
        for (int j = 0; j < 4; j++) acc[i][j] = 0ull;
    mma_chunk(Xs, Ws, tx, ty, acc);

    const float4 c0 = ((const float4*)b1b)[tx * 2];
    const float4 c1 = ((const float4*)b1b)[tx * 2 + 1];

    __syncthreads();   // all reads of Xs/Ws done before overwrite

    // ---- h1 tile -> Xs (zeros beyond M); Ws <- W2a ----
#pragma unroll
    for (int i = 0; i < 8; i++) {
        const int r = ty + 32 * i;
        const int m = m0 + r;
        float4 o0 = make_float4(0.f, 0.f, 0.f, 0.f);
        float4 o1 = make_float4(0.f, 0.f, 0.f, 0.f);
        if (m < M) {
            const float2 e0 = unpack2(acc[i][0]);
            const float2 e1 = unpack2(acc[i][1]);
            const float2 e2 = unpack2(acc[i][2]);
            const float2 e3 = unpack2(acc[i][3]);
            o0.x = lrelu(e0.x + c0.x); o0.y = lrelu(e0.y + c0.y);
            o0.z = lrelu(e1.x + c0.z); o0.w = lrelu(e1.y + c0.w);
            o1.x = lrelu(e2.x + c1.x); o1.y = lrelu(e2.y + c1.y);
            o1.z = lrelu(e3.x + c1.z); o1.w = lrelu(e3.y + c1.w);
        }
        *(float4*)&Xs[r * S + tx * 8]     = o0;
        *(float4*)&Xs[r * S + tx * 8 + 4] = o1;
    }
    for (int i = tid; i < 64 * 16; i += 256)
        ((float4*)Ws)[i] = ((const float4*)W2a)[i];
    __syncthreads();

    // ---- Stage 2: p2 = h1 @ W2a ----
#pragma unroll
    for (int i = 0; i < 8; i++)
#pragma unroll
        for (int j = 0; j < 4; j++) acc[i][j] = 0ull;
    mma_chunk(Xs, Ws, tx, ty, acc);

#pragma unroll
    for (int i = 0; i < 8; i++) {
        const int m = m0 + ty + 32 * i;
        if (m < M) {
            const float2 e0 = unpack2(acc[i][0]);
            const float2 e1 = unpack2(acc[i][1]);
            const float2 e2 = unpack2(acc[i][2]);
            const float2 e3 = unpack2(acc[i][3]);
            float4 o0, o1;
            o0.x = e0.x; o0.y = e0.y; o0.z = e1.x; o0.w = e1.y;
            o1.x = e2.x; o1.y = e2.y; o1.z = e3.x; o1.w = e3.y;
            float4* yr = (float4*)(p2 + (size_t)m * 64);
            yr[tx * 2]     = o0;
            yr[tx * 2 + 1] = o1;
            uint4 pk;
            pk.x = h2_bits(__floats2half2_rn(o0.x, o0.y));
            pk.y = h2_bits(__floats2half2_rn(o0.z, o0.w));
            pk.z = h2_bits(__floats2half2_rn(o1.x, o1.y));
            pk.w = h2_bits(__floats2half2_rn(o1.z, o1.w));
            *(uint4*)&p2_16[(size_t)m * 32 + tx * 4] = pk;
        }
    }
}

// ---------------------------------------------------------------------------
extern "C" void kernel_launch(void* const* d_in, const int* in_sizes, int n_in,
                              void* d_out, int out_size) {
    const float* h   = (const float*)d_in[0];
    const int*   ei  = (const int*)d_in[1];
    const float* W1a = (const float*)d_in[2];
    const float* b1a = (const float*)d_in[3];
    const float* W1b = (const float*)d_in[4];
    const float* b1b = (const float*)d_in[5];
    const float* W2a = (const float*)d_in[6];
    const float* b2a = (const float*)d_in[7];
    const float* W2b = (const float*)d_in[8];
    const float* b2b = (const float*)d_in[9];
    float* out = (float*)d_out;

    const int M = in_sizes[0] / IN_DIM;   // 100000
    const int E = in_sizes[1] / 2;        // 1600000
    const int* src = ei;
    const int* dst = ei + E;

    float *p, *agg;
    __half2* p16;
    int *deg, *row, *cur, *adj;
    u64* bstate;
    cudaGetSymbolAddress((void**)&p,      g_p);
    cudaGetSymbolAddress((void**)&p16,    g_p16);
    cudaGetSymbolAddress((void**)&agg,    g_agg);
    cudaGetSymbolAddress((void**)&deg,    g_deg);
    cudaGetSymbolAddress((void**)&row,    g_row);
    cudaGetSymbolAddress((void**)&cur,    g_cur);
    cudaGetSymbolAddress((void**)&bstate, g_bstate);
    cudaGetSymbolAddress((void**)&adj,    g_adj);

    const int nblk = (M + 1023) / 1024;

    const int gblocks = (M + 255) / 256;        // 391
    const int wblocks = (M * 32 + 255) / 256;   // warp-per-node gather
    const int smem128 = (256 * 68 + 128 * 64) * 4;  // 102400 B
    const int smem64  = (256 * 68 + 64 * 64)  * 4;  // 86016 B

    cudaFuncSetAttribute(gemm64_kernel<128, false>,
                         cudaFuncAttributeMaxDynamicSharedMemorySize, smem128);
    cudaFuncSetAttribute(gemm64_kernel<64, true>,
                         cudaFuncAttributeMaxDynamicSharedMemorySize, smem64);
    cudaFuncSetAttribute(fused_mid_kernel,
                         cudaFuncAttributeMaxDynamicSharedMemorySize, smem64);

    // ---- CSR build + layer-1 producer (gemm128 stays at launch index 3
    //      so the ncu window lands on it) ----
    k_zero<<<(M + 255) / 256, 256>>>(deg, bstate, M);
    k_hist<<<(E + 255) / 256, 256>>>(dst, deg, E);
    k_scanLB<<<nblk, 1024>>>(deg, row, cur, bstate, M, nblk);
    gemm64_kernel<128, false><<<gblocks, 256, smem128>>>(h, nullptr, nullptr,
                                                         W1a, nullptr, p, p16, M);
    k_fill<<<(E + 255) / 256, 256>>>(src, dst, cur, adj, E);

    k_gather<<<wblocks, 256>>>(p16, row, adj, agg, M);
    fused_mid_kernel<<<gblocks, 256, smem64>>>(p, agg, b1a, W1b, b1b, W2a,
                                               p, p16, M);
    k_gather<<<wblocks, 256>>>(p16, row, adj, agg, M);
    gemm64_kernel<64, true><<<gblocks, 256, smem64>>>(p, agg, b2a,
                                                      W2b, b2b, out, nullptr, M);
}

// round 17
// speedup vs baseline: 1.1889x; 1.0172x over previous
#include <cuda_runtime.h>
#include <cuda_fp16.h>

#define HID 64
#define IN_DIM 128
#define NMAX 100000
#define EMAX 1600000

typedef unsigned long long u64;

// Scratch (__device__ globals: allocation-free rule)
__device__ float   g_p[NMAX * HID];
__device__ __half2 g_p16[NMAX * HID / 2];
__device__ float   g_agg[NMAX * HID];
__device__ int     g_deg[NMAX];
__device__ int     g_row[NMAX + 1];
__device__ int     g_cur[NMAX];
__device__ u64     g_bstate[128];
__device__ int     g_adj[EMAX];

static __device__ __forceinline__ unsigned h2_bits(__half2 h) {
    unsigned u;
    *(__half2*)&u = h;
    return u;
}

static __device__ __forceinline__ float lrelu(float v) {
    return v > 0.f ? v : 0.01f * v;
}

// --- packed dual-fp32 FMA (Blackwell f32x2; 2 MACs per issue slot) ---------
static __device__ __forceinline__ u64 pack2(float a, float b) {
    u64 r;
    asm("mov.b64 %0, {%1, %2};" : "=l"(r) : "f"(a), "f"(b));
    return r;
}
static __device__ __forceinline__ void fma2(u64& acc, u64 a, u64 b) {
    asm("fma.rn.f32x2 %0, %1, %2, %0;" : "+l"(acc) : "l"(a), "l"(b));
}
static __device__ __forceinline__ float2 unpack2(u64 v) {
    float2 f;
    asm("mov.b64 {%0, %1}, %2;" : "=f"(f.x), "=f"(f.y) : "l"(v));
    return f;
}

// ---------------------------------------------------------------------------
// W smem layout (bank-conflict-free):
// For each k-row (64 floats), position c*32 + t*4 + u holds W[k][8t + 4c + u]
// (c in {0,1}, t in 0..7, u in 0..3). Reader tx loads its 8 columns
// j = 8*tx .. 8*tx+7 via two LDS.128 at tx*4 and 32 + tx*4: 8 lanes x 16B
// contiguous = 128B line, degree-1 (vs tx*8 row-major = 32B spacing, degree-2).
// ---------------------------------------------------------------------------
template <int K>
static __device__ __forceinline__
void load_W_perm(const float* __restrict__ W, float* __restrict__ Ws, int tid) {
    for (int i = tid; i < K * 16; i += 256) {
        const int k = i >> 4, r = i & 15;
        const int c = r >> 3, t = r & 7;
        const float4 v = *(const float4*)&W[k * 64 + 8 * t + 4 * c];
        *(float4*)&Ws[k * 64 + c * 32 + t * 4] = v;
    }
}

// ---------------------------------------------------------------------------
// CSR build
// ---------------------------------------------------------------------------
__global__ void k_zero(int* deg, u64* bstate, int n) {
    int i = blockIdx.x * blockDim.x + threadIdx.x;
    if (i < n) deg[i] = 0;
    if (i < 128) bstate[i] = 0ull;
}

__global__ void k_hist(const int* __restrict__ dst, int* deg, int E) {
    int i = blockIdx.x * blockDim.x + threadIdx.x;
    if (i < E) atomicAdd(&deg[dst[i]], 1);
}

// Single-kernel exclusive scan of deg -> row & cur, via decoupled lookback.
__global__ void k_scanLB(const int* __restrict__ deg,
                         int* row, int* cur, u64* bstate,
                         int M, int nblk) {
    __shared__ int wsum[32];
    __shared__ int s_prev;
    const int tid = threadIdx.x;
    const int bid = blockIdx.x;
    const int i = bid * 1024 + tid;
    const int v = (i < M) ? deg[i] : 0;

    int x = v;
#pragma unroll
    for (int o = 1; o < 32; o <<= 1) {
        int t = __shfl_up_sync(0xffffffffu, x, o);
        if ((tid & 31) >= o) x += t;
    }
    if ((tid & 31) == 31) wsum[tid >> 5] = x;
    __syncthreads();
    if (tid < 32) {
        int y = wsum[tid];
#pragma unroll
        for (int o = 1; o < 32; o <<= 1) {
            int t = __shfl_up_sync(0xffffffffu, y, o);
            if (tid >= o) y += t;
        }
        wsum[tid] = y;
    }
    __syncthreads();
    const int base = (tid >= 32) ? wsum[(tid >> 5) - 1] : 0;
    const int incl = x + base;
    const int btotal = wsum[31];

    if (tid == 0) {
        u64 st = ((u64)(bid == 0 ? 2 : 1) << 62) | (unsigned)btotal;
        atomicExch(&bstate[bid], st);
        if (bid == 0) s_prev = 0;
    }

    if (bid > 0 && tid < 32) {
        int base_idx = bid - 1;
        int running = 0;
        while (true) {
            const int idx = base_idx - tid;
            u64 st;
            unsigned flag;
            do {
                st = (idx >= 0) ? atomicAdd(&bstate[idx], 0ull)
                                : ((u64)2 << 62);
                flag = (unsigned)(st >> 62);
            } while (flag == 0);
            const unsigned pre_mask = __ballot_sync(0xffffffffu, flag == 2);
            int val = (int)(st & 0xffffffffu);
            if (pre_mask) {
                const int p = __ffs(pre_mask) - 1;
                int contrib = (tid <= p) ? val : 0;
#pragma unroll
                for (int o = 16; o; o >>= 1)
                    contrib += __shfl_down_sync(0xffffffffu, contrib, o);
                running += __shfl_sync(0xffffffffu, contrib, 0);
                break;
            } else {
                int contrib = val;
#pragma unroll
                for (int o = 16; o; o >>= 1)
                    contrib += __shfl_down_sync(0xffffffffu, contrib, o);
                running += __shfl_sync(0xffffffffu, contrib, 0);
                base_idx -= 32;
            }
        }
        if (tid == 0) {
            s_prev = running;
            atomicExch(&bstate[bid], ((u64)2 << 62) | (unsigned)(running + btotal));
        }
    }
    __syncthreads();

    const int prev = s_prev;
    if (i < M) {
        const int r = prev + incl - v;
        row[i] = r;
        cur[i] = r;
    }
    if (bid == nblk - 1 && tid == 1023) row[M] = prev + incl;
}

__global__ void k_fill(const int* __restrict__ src, const int* __restrict__ dst,
                       int* cur, int* adj, int E) {
    int i = blockIdx.x * blockDim.x + threadIdx.x;
    if (i < E) {
        int pos = atomicAdd(&cur[dst[i]], 1);
        adj[pos] = src[i];
    }
}

// ---------------------------------------------------------------------------
// Gather-sum over fp16 rows (warp per node, MLP=4)
// ---------------------------------------------------------------------------
__global__ __launch_bounds__(256)
void k_gather(const __half2* __restrict__ p16,
              const int* __restrict__ row,
              const int* __restrict__ adj,
              float* __restrict__ agg, int M) {
    const int w = (blockIdx.x * blockDim.x + threadIdx.x) >> 5;
    if (w >= M) return;
    const int lane = threadIdx.x & 31;
    const int beg = __ldg(&row[w]);
    const int end = __ldg(&row[w + 1]);
    float sx = 0.f, sy = 0.f;
    int j = beg;
    for (; j + 3 < end; j += 4) {
        const int u0 = __ldg(&adj[j]);
        const int u1 = __ldg(&adj[j + 1]);
        const int u2 = __ldg(&adj[j + 2]);
        const int u3 = __ldg(&adj[j + 3]);
        const float2 f0 = __half22float2(__ldg(&p16[(size_t)u0 * 32 + lane]));
        const float2 f1 = __half22float2(__ldg(&p16[(size_t)u1 * 32 + lane]));
        const float2 f2 = __half22float2(__ldg(&p16[(size_t)u2 * 32 + lane]));
        const float2 f3 = __half22float2(__ldg(&p16[(size_t)u3 * 32 + lane]));
        sx += (f0.x + f1.x) + (f2.x + f3.x);
        sy += (f0.y + f1.y) + (f2.y + f3.y);
    }
    for (; j < end; j++) {
        const int u = __ldg(&adj[j]);
        const float2 f = __half22float2(__ldg(&p16[(size_t)u * 32 + lane]));
        sx += f.x;
        sy += f.y;
    }
    ((float2*)agg)[(size_t)w * 32 + lane] = make_float2(sx, sy);
}

// ---------------------------------------------------------------------------
// f32x2 core over a 256-row tile, 64-wide K-chunk: 8 rows x 8 cols per thread.
// X read as float4 (4 k's per LDS.128); W read from the permuted layout
// (conflict-free). Accumulation order over k is unchanged (k, k+1, k+2, k+3).
// ---------------------------------------------------------------------------
static __device__ __forceinline__
void mma_chunk(const float* __restrict__ Xs, const float* __restrict__ Wc,
               int tx, int ty, u64 acc[8][4]) {
    constexpr int S = 68;
#pragma unroll
    for (int k = 0; k < 64; k += 4) {
        float4 x[8];
#pragma unroll
        for (int i = 0; i < 8; i++)
            x[i] = *(const float4*)&Xs[(ty + 32 * i) * S + k];
#pragma unroll
        for (int kk = 0; kk < 4; kk += 2) {
            const float* wr0 = Wc + (k + kk) * 64;
            const float* wr1 = Wc + (k + kk + 1) * 64;
            const ulonglong2 wa01 = *(const ulonglong2*)&wr0[tx * 4];
            const ulonglong2 wa23 = *(const ulonglong2*)&wr0[32 + tx * 4];
            const ulonglong2 wb01 = *(const ulonglong2*)&wr1[tx * 4];
            const ulonglong2 wb23 = *(const ulonglong2*)&wr1[32 + tx * 4];
#pragma unroll
            for (int i = 0; i < 8; i++) {
                const float xs0 = (kk == 0) ? x[i].x : x[i].z;
                const float xs1 = (kk == 0) ? x[i].y : x[i].w;
                const u64 xa = pack2(xs0, xs0);
                const u64 xb = pack2(xs1, xs1);
                fma2(acc[i][0], xa, wa01.x); fma2(acc[i][1], xa, wa01.y);
                fma2(acc[i][2], xa, wa23.x); fma2(acc[i][3], xa, wa23.y);
                fma2(acc[i][0], xb, wb01.x); fma2(acc[i][1], xb, wb01.y);
                fma2(acc[i][2], xb, wb23.x); fma2(acc[i][3], xb, wb23.y);
            }
        }
    }
}

// ---------------------------------------------------------------------------
// GEMM: Y[M,64] = f(X) @ W[K,64]   (block tile 256x64, 256 threads)
// Xs holds a 64-wide K-chunk (256*68 floats); W fully resident (permuted).
// smem: K=128 -> 102.4KB (2 blocks/SM, 16 warps); K=64 -> 86KB (2 blocks/SM).
// CONSUME=false: x = X1;              Y = X@W;  also writes P16 = fp16(Y)
// CONSUME=true : x = relu(X1+X2+ba);  Y = leaky(X@W + bb)   (K=64 only)
// ---------------------------------------------------------------------------
template <int K, bool CONSUME>
__global__ __launch_bounds__(256, 2)
void gemm64_kernel(const float* __restrict__ X1,
                   const float* __restrict__ X2,
                   const float* __restrict__ ba,
                   const float* __restrict__ W,
                   const float* __restrict__ bb,
                   float* __restrict__ Y,
                   __half2* __restrict__ P16,
                   int M) {
    constexpr int S = 68;
    extern __shared__ float smem[];
    float* Xs = smem;             // 256 * 68 (one 64-wide K chunk)
    float* Ws = smem + 256 * S;   // K * 64 (full, permuted)

    const int tid = threadIdx.x;
    const int m0  = blockIdx.x * 256;
    const int tx  = tid & 7;
    const int ty  = tid >> 3;

    load_W_perm<K>(W, Ws, tid);

    u64 acc[8][4];
#pragma unroll
    for (int i = 0; i < 8; i++)
#pragma unroll
        for (int j = 0; j < 4; j++) acc[i][j] = 0ull;

#pragma unroll
    for (int kk = 0; kk < K; kk += 64) {
        if (kk > 0) __syncthreads();   // all warps done with previous chunk
        // Load 64-wide X chunk (fused transform)
        for (int i = tid; i < 256 * 16; i += 256) {
            const int r  = i / 16;
            const int kc = i % 16;
            const int m  = m0 + r;
            float4 v = make_float4(0.f, 0.f, 0.f, 0.f);
            if (m < M) {
                v = ((const float4*)(X1 + (size_t)m * K + kk))[kc];
                if (CONSUME) {
                    float4 a = ((const float4*)(X2 + (size_t)m * K + kk))[kc];
                    float4 b = ((const float4*)(ba + kk))[kc];
                    v.x = fmaxf(v.x + a.x + b.x, 0.f);
                    v.y = fmaxf(v.y + a.y + b.y, 0.f);
                    v.z = fmaxf(v.z + a.z + b.z, 0.f);
                    v.w = fmaxf(v.w + a.w + b.w, 0.f);
                }
            }
            *(float4*)&Xs[r * S + kc * 4] = v;
        }
        __syncthreads();
        mma_chunk(Xs, Ws + kk * 64, tx, ty, acc);
    }

    float4 b0 = make_float4(0.f, 0.f, 0.f, 0.f);
    float4 b1 = make_float4(0.f, 0.f, 0.f, 0.f);
    if (CONSUME) {
        b0 = ((const float4*)bb)[tx * 2];
        b1 = ((const float4*)bb)[tx * 2 + 1];
    }

#pragma unroll
    for (int i = 0; i < 8; i++) {
        const int m = m0 + ty + 32 * i;
        if (m < M) {
            const float2 e0 = unpack2(acc[i][0]);
            const float2 e1 = unpack2(acc[i][1]);
            const float2 e2 = unpack2(acc[i][2]);
            const float2 e3 = unpack2(acc[i][3]);
            float4 o0, o1;
            o0.x = e0.x + b0.x; o0.y = e0.y + b0.y;
            o0.z = e1.x + b0.z; o0.w = e1.y + b0.w;
            o1.x = e2.x + b1.x; o1.y = e2.y + b1.y;
            o1.z = e3.x + b1.z; o1.w = e3.y + b1.w;
            if (CONSUME) {
                o0.x = lrelu(o0.x); o0.y = lrelu(o0.y);
                o0.z = lrelu(o0.z); o0.w = lrelu(o0.w);
                o1.x = lrelu(o1.x); o1.y = lrelu(o1.y);
                o1.z = lrelu(o1.z); o1.w = lrelu(o1.w);
            }
            float4* yr = (float4*)(Y + (size_t)m * 64);
            yr[tx * 2]     = o0;
            yr[tx * 2 + 1] = o1;
            if (!CONSUME) {
                uint4 pk;
                pk.x = h2_bits(__floats2half2_rn(o0.x, o0.y));
                pk.y = h2_bits(__floats2half2_rn(o0.z, o0.w));
                pk.z = h2_bits(__floats2half2_rn(o1.x, o1.y));
                pk.w = h2_bits(__floats2half2_rn(o1.z, o1.w));
                *(uint4*)&P16[(size_t)m * 32 + tx * 4] = pk;
            }
        }
    }
}

// ---------------------------------------------------------------------------
// Fused mid kernel (256-row tile, 256 threads):
//   h1 = leaky( relu(p + agg + b1a) @ W1b + b1b )   (stays in smem)
//   p2 = h1 @ W2a;  p2_16 = fp16(p2)
// ---------------------------------------------------------------------------
__global__ __launch_bounds__(256, 2)
void fused_mid_kernel(const float* __restrict__ p,
                      const float* __restrict__ agg,
                      const float* __restrict__ b1a,
                      const float* __restrict__ W1b,
                      const float* __restrict__ b1b,
                      const float* __restrict__ W2a,
                      float* __restrict__ p2,
                      __half2* __restrict__ p2_16,
                      int M) {
    constexpr int S = 68, KC = 16;
    extern __shared__ float smem[];
    float* Xs = smem;             // 256 * 68
    float* Ws = smem + 256 * S;   // 64 * 64 (permuted)

    const int tid = threadIdx.x;
    const int m0  = blockIdx.x * 256;
    const int tx  = tid & 7;
    const int ty  = tid >> 3;

    // ---- Stage 1 load: Ws = perm(W1b), Xs = relu(p + agg + b1a) ----
    load_W_perm<64>(W1b, Ws, tid);
    for (int i = tid; i < 256 * KC; i += 256) {
        const int r  = i / KC;
        const int kc = i % KC;
        const int m  = m0 + r;
        float4 v = make_float4(0.f, 0.f, 0.f, 0.f);
        if (m < M) {
            v = ((const float4*)(p + (size_t)m * 64))[kc];
            float4 a = ((const float4*)(agg + (size_t)m * 64))[kc];
            float4 b = ((const float4*)b1a)[kc];
            v.x = fmaxf(v.x + a.x + b.x, 0.f);
            v.y = fmaxf(v.y + a.y + b.y, 0.f);
            v.z = fmaxf(v.z + a.z + b.z, 0.f);
            v.w = fmaxf(v.w + a.w + b.w, 0.f);
        }
        *(float4*)&Xs[r * S + kc * 4] = v;
    }
    __syncthreads();

    u64 acc[8][4];
#pragma unroll
    for (int i = 0; i < 8; i++)
#pragma unroll
        for (int j = 0; j < 4; j++) acc[i][j] = 0ull;
    mma_chunk(Xs, Ws, tx, ty, acc);

    const float4 c0 = ((const float4*)b1b)[tx * 2];
    const float4 c1 = ((const float4*)b1b)[tx * 2 + 1];

    __syncthreads();   // all reads of Xs/Ws done before overwrite

    // ---- h1 tile -> Xs (zeros beyond M); Ws <- perm(W2a) ----
#pragma unroll
    for (int i = 0; i < 8; i++) {
        const int r = ty + 32 * i;
        const int m = m0 + r;
        float4 o0 = make_float4(0.f, 0.f, 0.f, 0.f);
        float4 o1 = make_float4(0.f, 0.f, 0.f, 0.f);
        if (m < M) {
            const float2 e0 = unpack2(acc[i][0]);
            const float2 e1 = unpack2(acc[i][1]);
            const float2 e2 = unpack2(acc[i][2]);
            const float2 e3 = unpack2(acc[i][3]);
            o0.x = lrelu(e0.x + c0.x); o0.y = lrelu(e0.y + c0.y);
            o0.z = lrelu(e1.x + c0.z); o0.w = lrelu(e1.y + c0.w);
            o1.x = lrelu(e2.x + c1.x); o1.y = lrelu(e2.y + c1.y);
            o1.z = lrelu(e3.x + c1.z); o1.w = lrelu(e3.y + c1.w);
        }
        *(float4*)&Xs[r * S + tx * 8]     = o0;
        *(float4*)&Xs[r * S + tx * 8 + 4] = o1;
    }
    load_W_perm<64>(W2a, Ws, tid);
    __syncthreads();

    // ---- Stage 2: p2 = h1 @ W2a ----
#pragma unroll
    for (int i = 0; i < 8; i++)
#pragma unroll
        for (int j = 0; j < 4; j++) acc[i][j] = 0ull;
    mma_chunk(Xs, Ws, tx, ty, acc);

#pragma unroll
    for (int i = 0; i < 8; i++) {
        const int m = m0 + ty + 32 * i;
        if (m < M) {
            const float2 e0 = unpack2(acc[i][0]);
            const float2 e1 = unpack2(acc[i][1]);
            const float2 e2 = unpack2(acc[i][2]);
            const float2 e3 = unpack2(acc[i][3]);
            float4 o0, o1;
            o0.x = e0.x; o0.y = e0.y; o0.z = e1.x; o0.w = e1.y;
            o1.x = e2.x; o1.y = e2.y; o1.z = e3.x; o1.w = e3.y;
            float4* yr = (float4*)(p2 + (size_t)m * 64);
            yr[tx * 2]     = o0;
            yr[tx * 2 + 1] = o1;
            uint4 pk;
            pk.x = h2_bits(__floats2half2_rn(o0.x, o0.y));
            pk.y = h2_bits(__floats2half2_rn(o0.z, o0.w));
            pk.z = h2_bits(__floats2half2_rn(o1.x, o1.y));
            pk.w = h2_bits(__floats2half2_rn(o1.z, o1.w));
            *(uint4*)&p2_16[(size_t)m * 32 + tx * 4] = pk;
        }
    }
}

// ---------------------------------------------------------------------------
extern "C" void kernel_launch(void* const* d_in, const int* in_sizes, int n_in,
                              void* d_out, int out_size) {
    const float* h   = (const float*)d_in[0];
    const int*   ei  = (const int*)d_in[1];
    const float* W1a = (const float*)d_in[2];
    const float* b1a = (const float*)d_in[3];
    const float* W1b = (const float*)d_in[4];
    const float* b1b = (const float*)d_in[5];
    const float* W2a = (const float*)d_in[6];
    const float* b2a = (const float*)d_in[7];
    const float* W2b = (const float*)d_in[8];
    const float* b2b = (const float*)d_in[9];
    float* out = (float*)d_out;

    const int M = in_sizes[0] / IN_DIM;   // 100000
    const int E = in_sizes[1] / 2;        // 1600000
    const int* src = ei;
    const int* dst = ei + E;

    float *p, *agg;
    __half2* p16;
    int *deg, *row, *cur, *adj;
    u64* bstate;
    cudaGetSymbolAddress((void**)&p,      g_p);
    cudaGetSymbolAddress((void**)&p16,    g_p16);
    cudaGetSymbolAddress((void**)&agg,    g_agg);
    cudaGetSymbolAddress((void**)&deg,    g_deg);
    cudaGetSymbolAddress((void**)&row,    g_row);
    cudaGetSymbolAddress((void**)&cur,    g_cur);
    cudaGetSymbolAddress((void**)&bstate, g_bstate);
    cudaGetSymbolAddress((void**)&adj,    g_adj);

    const int nblk = (M + 1023) / 1024;

    const int gblocks = (M + 255) / 256;        // 391
    const int wblocks = (M * 32 + 255) / 256;   // warp-per-node gather
    const int smem128 = (256 * 68 + 128 * 64) * 4;  // 102400 B
    const int smem64  = (256 * 68 + 64 * 64)  * 4;  // 86016 B

    cudaFuncSetAttribute(gemm64_kernel<128, false>,
                         cudaFuncAttributeMaxDynamicSharedMemorySize, smem128);
    cudaFuncSetAttribute(gemm64_kernel<64, true>,
                         cudaFuncAttributeMaxDynamicSharedMemorySize, smem64);
    cudaFuncSetAttribute(fused_mid_kernel,
                         cudaFuncAttributeMaxDynamicSharedMemorySize, smem64);

    // ---- CSR build + layer-1 producer (gemm128 stays at launch index 3
    //      so the ncu window lands on it) ----
    k_zero<<<(M + 255) / 256, 256>>>(deg, bstate, M);
    k_hist<<<(E + 255) / 256, 256>>>(dst, deg, E);
    k_scanLB<<<nblk, 1024>>>(deg, row, cur, bstate, M, nblk);
    gemm64_kernel<128, false><<<gblocks, 256, smem128>>>(h, nullptr, nullptr,
                                                         W1a, nullptr, p, p16, M);
    k_fill<<<(E + 255) / 256, 256>>>(src, dst, cur, adj, E);

    k_gather<<<wblocks, 256>>>(p16, row, adj, agg, M);
    fused_mid_kernel<<<gblocks, 256, smem64>>>(p, agg, b1a, W1b, b1b, W2a,
                                               p, p16, M);
    k_gather<<<wblocks, 256>>>(p16, row, adj, agg, M);
    gemm64_kernel<64, true><<<gblocks, 256, smem64>>>(p, agg, b2a,
                                                      W2b, b2b, out, nullptr, M);
}